// round 14
// baseline (speedup 1.0000x reference)
#include <cuda_runtime.h>
#include <cuda_bf16.h>
#include <cstdint>
#include <cstddef>

// ---------------- problem constants ----------------
#define B_     256
#define T_     200
#define KDEP   5
#define EMB_   300
#define SMALLD 30
#define IN_DIM 360      // 300 + 30 + 30
#define IN0    390      // 360 + 30 (true K of GEMM0)
#define MEM_   300
#define BT_    (B_*T_)  // 51200
#define SLD    400      // S1 row stride (390 valid, pads zero) = GEMM0 padded K (25*16)
#define HLD    304      // h / S2 row stride (300 valid, pads zero) = GEMM1 padded K (19*16)

// ---------------- static device scratch (zero-initialized, never freed) ----------------
__device__ __align__(16) float g_x[(size_t)BT_*IN_DIM + 64]; // x [BT,360]; reused as S2 [BT,304]
__device__ __align__(16) float g_S[(size_t)BT_*SLD   + 64];  // S1 [BT,400]; cols 390..399 stay 0
__device__ __align__(16) float g_h[(size_t)BT_*HLD   + 64];  // h  [BT,304]; cols 300..303 stay 0
__device__ float g_invden[BT_];
__device__ float g_maskpad[BT_];

// ---------------- packed f32x2 helpers (Blackwell FFMA2 path) ----------------
__device__ __forceinline__ void ffma2(unsigned long long& d,
                                      unsigned long long a, unsigned long long b) {
    asm("fma.rn.f32x2 %0, %1, %2, %0;" : "+l"(d) : "l"(a), "l"(b));
}
__device__ __forceinline__ unsigned long long dup2(float v) {
    unsigned long long d;
    asm("mov.b64 %0, {%1, %1};" : "=l"(d) : "r"(__float_as_uint(v)));
    return d;
}
__device__ __forceinline__ float2 unpack2(unsigned long long v) {
    float2 f;
    asm("mov.b64 {%0, %1}, %2;" : "=f"(f.x), "=f"(f.y) : "l"(v));
    return f;
}

// ---------------- prep: embedding gathers + dep ragged sum ----------------
__global__ void prep_kernel(const int* __restrict__ words, const int* __restrict__ pos,
                            const int* __restrict__ ner, const int* __restrict__ dep_ids,
                            const int* __restrict__ dep_mask,
                            const float* __restrict__ word_emb, const float* __restrict__ pos_emb,
                            const float* __restrict__ ner_emb, const float* __restrict__ dep_emb)
{
    int warp = threadIdx.x >> 5, lane = threadIdx.x & 31;
    int i = blockIdx.x * 8 + warp;            // token index
    if (i >= BT_) return;

    const float* wrow = word_emb + (size_t)words[i] * EMB_;
    float* xrow = g_x + (size_t)i * IN_DIM;
    #pragma unroll
    for (int j = lane; j < EMB_; j += 32) xrow[j] = wrow[j];

    if (lane < SMALLD) {
        xrow[300 + lane] = pos_emb[pos[i] * SMALLD + lane];
        xrow[330 + lane] = ner_emb[ner[i] * SMALLD + lane];
        float s = 0.f; int cnt = 0;
        #pragma unroll
        for (int k = 0; k < KDEP; k++) {
            int m = dep_mask[i * KDEP + k];
            cnt += m;
            if (m) s += dep_emb[dep_ids[i * KDEP + k] * SMALLD + lane];
        }
        if (cnt == 0) s = dep_emb[lane];          // dep_emb[0]
        s += dep_emb[SMALLD + lane];              // + dep_emb[SELF_LOOP_ID=1]
        g_S[(size_t)i * SLD + IN_DIM + lane] = s; // cols 360..389
    }
}

// ---------------- denom (1/(rowsum+1)) + out_mask ----------------
__global__ void maskden_kernel(const int* __restrict__ adj, float* __restrict__ mask_out)
{
    __shared__ float rs_sh[T_];
    int b = blockIdx.x;
    int tid = threadIdx.x;                     // 256
    const int* Ab = adj + (size_t)b * T_ * T_;

    int col = 0;
    if (tid < T_) {
        for (int s = 0; s < T_; s++) col += Ab[s * T_ + tid];
    }
    int warp = tid >> 5, lane = tid & 31;
    for (int row = warp; row < T_; row += 8) {
        int acc = 0;
        for (int j = lane; j < T_; j += 32) acc += Ab[row * T_ + j];
        #pragma unroll
        for (int off = 16; off; off >>= 1) acc += __shfl_down_sync(0xffffffffu, acc, off);
        if (lane == 0) rs_sh[row] = (float)acc;
    }
    __syncthreads();
    if (tid < T_) {
        float rs = rs_sh[tid];
        g_invden[b * T_ + tid] = 1.0f / (rs + 1.0f);
        mask_out[b * T_ + tid] = ((rs + (float)col) == 0.0f) ? 1.0f : 0.0f;
    }
}

// ---------------- batched einsum: Out[b] = adj[b] @ X[b] + X[b] ----------------
// 128x64 tile, BK=8 (200 = 25*8, no K guards), 128 threads, 8m x 8n per thread
// via m-paired f32x2, double-buffered. Writes zeros into cols [Ncols, padz) of Out.
__global__ void __launch_bounds__(128, 4) einsum_kernel(const int* __restrict__ adj,
                              const float* __restrict__ X, int ldx,
                              float* __restrict__ Out, int ldo, int Ncols, int padz)
{
    __shared__ __align__(16) float As[2][8][132];  // [k][m] (m contiguous), padded
    __shared__ __align__(16) float Bs[2][8][68];   // [k][n], padded
    const int b  = blockIdx.z;
    const int m0 = blockIdx.y * 128;
    const int n0 = blockIdx.x * 64;
    const int tid = threadIdx.x;
    const int tr = tid >> 3, tc = tid & 7;         // 16 x 8 thread grid
    const int* Ab = adj + (size_t)b * (T_ * T_);
    const float* Xb = X + (size_t)b * T_ * ldx;

    float ra[8], rb[4];
    // ---- prologue: k0 = 0 into buffer 0 ----
    #pragma unroll
    for (int i = 0; i < 8; i++) {
        int slot = tid + i * 128;                  // 128m x 8k
        int r = slot >> 3, c = slot & 7;
        ra[i] = (m0 + r < T_) ? (float)Ab[(m0 + r) * T_ + c] : 0.f;
    }
    #pragma unroll
    for (int i = 0; i < 4; i++) {
        int idx = tid + i * 128;                   // 8k x 64n
        int r = idx >> 6, c = idx & 63;
        rb[i] = (n0 + c < Ncols) ? Xb[r * ldx + n0 + c] : 0.f;
    }
    #pragma unroll
    for (int i = 0; i < 8; i++) { int s = tid + i*128; As[0][s & 7][s >> 3] = ra[i]; }
    #pragma unroll
    for (int i = 0; i < 4; i++) { int s = tid + i*128; Bs[0][s >> 6][s & 63] = rb[i]; }
    __syncthreads();

    unsigned long long accp[4][8] = {};            // 4 m-pairs x 8 n
    const int NSTEP = T_ / 8;                      // 25
    for (int s = 0; s < NSTEP; s++) {
        int p = s & 1;
        if (s + 1 < NSTEP) {
            int k0 = (s + 1) * 8;
            #pragma unroll
            for (int i = 0; i < 8; i++) {
                int slot = tid + i * 128;
                int r = slot >> 3, c = slot & 7;
                ra[i] = (m0 + r < T_) ? (float)Ab[(m0 + r) * T_ + k0 + c] : 0.f;
            }
            #pragma unroll
            for (int i = 0; i < 4; i++) {
                int idx = tid + i * 128;
                int r = idx >> 6, c = idx & 63;
                rb[i] = (n0 + c < Ncols) ? Xb[(k0 + r) * ldx + n0 + c] : 0.f;
            }
        }
        #pragma unroll
        for (int kk = 0; kk < 8; kk++) {
            ulonglong2 a01 = *reinterpret_cast<const ulonglong2*>(&As[p][kk][tr * 8]);
            ulonglong2 a23 = *reinterpret_cast<const ulonglong2*>(&As[p][kk][tr * 8 + 4]);
            float4 b0 = *reinterpret_cast<const float4*>(&Bs[p][kk][tc * 8]);
            float4 b1 = *reinterpret_cast<const float4*>(&Bs[p][kk][tc * 8 + 4]);
            unsigned long long bd[8] = { dup2(b0.x), dup2(b0.y), dup2(b0.z), dup2(b0.w),
                                         dup2(b1.x), dup2(b1.y), dup2(b1.z), dup2(b1.w) };
            #pragma unroll
            for (int j = 0; j < 8; j++) { ffma2(accp[0][j], a01.x, bd[j]); }
            #pragma unroll
            for (int j = 0; j < 8; j++) { ffma2(accp[1][j], a01.y, bd[j]); }
            #pragma unroll
            for (int j = 0; j < 8; j++) { ffma2(accp[2][j], a23.x, bd[j]); }
            #pragma unroll
            for (int j = 0; j < 8; j++) { ffma2(accp[3][j], a23.y, bd[j]); }
        }
        if (s + 1 < NSTEP) {
            int q = 1 - p;
            #pragma unroll
            for (int i = 0; i < 8; i++) { int t = tid + i*128; As[q][t & 7][t >> 3] = ra[i]; }
            #pragma unroll
            for (int i = 0; i < 4; i++) { int t = tid + i*128; Bs[q][t >> 6][t & 63] = rb[i]; }
            __syncthreads();
        }
    }
    // ---- epilogue: Out = acc + X; zero-fill [Ncols, padz) ----
    #pragma unroll
    for (int mi = 0; mi < 4; mi++) {
        #pragma unroll
        for (int half = 0; half < 2; half++) {
            int m = m0 + tr * 8 + 2 * mi + half;
            if (m >= T_) continue;
            const float* xr = &Xb[(size_t)m * ldx];
            float* orow = &Out[((size_t)b * T_ + m) * ldo];
            #pragma unroll
            for (int j = 0; j < 8; j++) {
                float2 v = unpack2(accp[mi][j]);
                float a = half ? v.y : v.x;
                int n = n0 + tc * 8 + j;
                if (n < Ncols)     orow[n] = a + xr[n];
                else if (n < padz) orow[n] = 0.f;
            }
        }
    }
}

// ---------------- dense GEMM: C = relu((A@W + 2*bias) * invden) ----------------
// 128x64 tile, BK=16, 128 threads, 8m x 8n per thread via m-paired f32x2,
// double-buffered. M % 128 == 0. A read guard-free as float4 (lda = 16*nsteps,
// pad cols zero).
__global__ void __launch_bounds__(128, 4) dense_gemm_kernel(
        const float* __restrict__ A, int lda, int nsteps,
        const float* __restrict__ W, int K, int N,
        const float* __restrict__ bias, const float* __restrict__ invden,
        float* __restrict__ C, int ldc)
{
    __shared__ __align__(16) float As[2][16][132];   // [k][m] (m contiguous), padded
    __shared__ __align__(16) float Bs[2][16][68];    // [k][n], padded
    const int tid = threadIdx.x;
    const int m0 = blockIdx.y * 128;
    const int n0 = blockIdx.x * 64;
    const int tr = tid >> 3, tc = tid & 7;           // 16 x 8 thread grid

    float4 ra[4]; float rb[8];
    // ---- prologue: k0 = 0 into buffer 0 ----
    #pragma unroll
    for (int i = 0; i < 4; i++) {
        int slot = tid + i * 128;                    // 512 float4 slots = 128m x 4 quads
        int r = slot >> 2, cq = slot & 3;
        ra[i] = *reinterpret_cast<const float4*>(&A[(size_t)(m0 + r) * lda + cq * 4]);
    }
    #pragma unroll
    for (int i = 0; i < 8; i++) {
        int idx = tid + i * 128;                     // 16k x 64n
        int r = idx >> 6, c = idx & 63;
        rb[i] = (r < K && n0 + c < N) ? W[(size_t)r * N + n0 + c] : 0.f;
    }
    #pragma unroll
    for (int i = 0; i < 4; i++) {
        int slot = tid + i * 128; int r = slot >> 2, cq = slot & 3;
        As[0][cq*4+0][r] = ra[i].x; As[0][cq*4+1][r] = ra[i].y;
        As[0][cq*4+2][r] = ra[i].z; As[0][cq*4+3][r] = ra[i].w;
    }
    #pragma unroll
    for (int i = 0; i < 8; i++) { int t = tid + i*128; Bs[0][t >> 6][t & 63] = rb[i]; }
    __syncthreads();

    unsigned long long accp[4][8] = {};              // 4 m-pairs x 8 n
    for (int s = 0; s < nsteps; s++) {
        int p = s & 1;
        if (s + 1 < nsteps) {
            int k0 = (s + 1) * 16;
            #pragma unroll
            for (int i = 0; i < 4; i++) {
                int slot = tid + i * 128; int r = slot >> 2, cq = slot & 3;
                ra[i] = *reinterpret_cast<const float4*>(&A[(size_t)(m0 + r) * lda + k0 + cq * 4]);
            }
            #pragma unroll
            for (int i = 0; i < 8; i++) {
                int idx = tid + i * 128; int r = idx >> 6, c = idx & 63;
                int gk = k0 + r;
                rb[i] = (gk < K && n0 + c < N) ? W[(size_t)gk * N + n0 + c] : 0.f;
            }
        }
        #pragma unroll
        for (int kk = 0; kk < 16; kk++) {
            ulonglong2 a01 = *reinterpret_cast<const ulonglong2*>(&As[p][kk][tr * 8]);
            ulonglong2 a23 = *reinterpret_cast<const ulonglong2*>(&As[p][kk][tr * 8 + 4]);
            float4 b0 = *reinterpret_cast<const float4*>(&Bs[p][kk][tc * 8]);
            float4 b1 = *reinterpret_cast<const float4*>(&Bs[p][kk][tc * 8 + 4]);
            unsigned long long bd[8] = { dup2(b0.x), dup2(b0.y), dup2(b0.z), dup2(b0.w),
                                         dup2(b1.x), dup2(b1.y), dup2(b1.z), dup2(b1.w) };
            #pragma unroll
            for (int j = 0; j < 8; j++) { ffma2(accp[0][j], a01.x, bd[j]); }
            #pragma unroll
            for (int j = 0; j < 8; j++) { ffma2(accp[1][j], a01.y, bd[j]); }
            #pragma unroll
            for (int j = 0; j < 8; j++) { ffma2(accp[2][j], a23.x, bd[j]); }
            #pragma unroll
            for (int j = 0; j < 8; j++) { ffma2(accp[3][j], a23.y, bd[j]); }
        }
        if (s + 1 < nsteps) {
            int q = 1 - p;
            #pragma unroll
            for (int i = 0; i < 4; i++) {
                int slot = tid + i * 128; int r = slot >> 2, cq = slot & 3;
                As[q][cq*4+0][r] = ra[i].x; As[q][cq*4+1][r] = ra[i].y;
                As[q][cq*4+2][r] = ra[i].z; As[q][cq*4+3][r] = ra[i].w;
            }
            #pragma unroll
            for (int i = 0; i < 8; i++) { int t = tid + i*128; Bs[q][t >> 6][t & 63] = rb[i]; }
            __syncthreads();
        }
    }

    // ---- epilogue: relu((acc + 2b) * invden) ----
    float bn[8];
    #pragma unroll
    for (int j = 0; j < 8; j++) {
        int n = n0 + tc * 8 + j;
        bn[j] = (n < N) ? 2.0f * bias[n] : 0.f;
    }
    const int nb = n0 + tc * 8;
    #pragma unroll
    for (int mi = 0; mi < 4; mi++) {
        int me = m0 + tr * 8 + 2 * mi;
        float inv_e = invden[me], inv_o = invden[me + 1];
        float ve[8], vo[8];
        #pragma unroll
        for (int j = 0; j < 8; j++) {
            float2 v = unpack2(accp[mi][j]);
            ve[j] = fmaxf((v.x + bn[j]) * inv_e, 0.f);
            vo[j] = fmaxf((v.y + bn[j]) * inv_o, 0.f);
        }
        float* ce = &C[(size_t)me * ldc + nb];
        float* co = &C[(size_t)(me + 1) * ldc + nb];
        if (nb + 8 <= N) {
            *reinterpret_cast<float4*>(ce)     = make_float4(ve[0], ve[1], ve[2], ve[3]);
            *reinterpret_cast<float4*>(ce + 4) = make_float4(ve[4], ve[5], ve[6], ve[7]);
            *reinterpret_cast<float4*>(co)     = make_float4(vo[0], vo[1], vo[2], vo[3]);
            *reinterpret_cast<float4*>(co + 4) = make_float4(vo[4], vo[5], vo[6], vo[7]);
        } else {
            #pragma unroll
            for (int j = 0; j < 8; j++) {
                if (nb + j < N) { ce[j] = ve[j]; co[j] = vo[j]; }
            }
        }
    }
}

// ---------------- launch ----------------
extern "C" void kernel_launch(void* const* d_in, const int* in_sizes, int n_in,
                              void* d_out, int out_size)
{
    const int* adj      = (const int*)d_in[0];
    const int* words    = (const int*)d_in[1];
    const int* pos      = (const int*)d_in[2];
    const int* ner      = (const int*)d_in[3];
    const int* dep_ids  = (const int*)d_in[4];
    const int* dep_mask = (const int*)d_in[5];
    int base = n_in - 8;                    // trailing 8 arrays are fixed
    const float* word_emb = (const float*)d_in[base + 0];
    const float* pos_emb  = (const float*)d_in[base + 1];
    const float* ner_emb  = (const float*)d_in[base + 2];
    const float* dep_emb  = (const float*)d_in[base + 3];
    const float* W0_w     = (const float*)d_in[base + 4];
    const float* W0_b     = (const float*)d_in[base + 5];
    const float* W1_w     = (const float*)d_in[base + 6];
    const float* W1_b     = (const float*)d_in[base + 7];

    float* out = (float*)d_out;

    void *px, *pS, *ph, *pinv, *pmaskpad;
    cudaGetSymbolAddress(&px, g_x);
    cudaGetSymbolAddress(&pS, g_S);
    cudaGetSymbolAddress(&ph, g_h);
    cudaGetSymbolAddress(&pinv, g_invden);
    cudaGetSymbolAddress(&pmaskpad, g_maskpad);
    float* gx   = (float*)px;
    float* gS   = (float*)pS;
    float* gh   = (float*)ph;
    float* ginv = (float*)pinv;

    float* mask_out = ((long long)out_size >= (long long)BT_ * MEM_ + BT_)
                        ? (out + (size_t)BT_ * MEM_) : (float*)pmaskpad;

    // 1) embeddings + dep columns of S1
    prep_kernel<<<BT_ / 8, 256>>>(words, pos, ner, dep_ids, dep_mask,
                                  word_emb, pos_emb, ner_emb, dep_emb);

    // 2) denom + out_mask
    maskden_kernel<<<B_, 256>>>(adj, mask_out);

    // 3) S1[:, :360] = A@x + x   (cols 360..389 from prep; 390..399 static zero)
    einsum_kernel<<<dim3(6, 2, B_), 128>>>(adj, gx, IN_DIM, gS, SLD, IN_DIM, IN_DIM);

    // 4) h = relu((S1 @ W0 + 2*b0) * invden)   K=390 padded to 400 (25 steps)
    dense_gemm_kernel<<<dim3(5, BT_ / 128), 128>>>(gS, SLD, 25, W0_w, IN0, MEM_,
                                                   W0_b, ginv, gh, HLD);

    // 5) S2 = A@h + h  (into g_x, stride 304; cols 300..303 zero-filled)
    einsum_kernel<<<dim3(5, 2, B_), 128>>>(adj, gh, HLD, gx, HLD, MEM_, HLD);

    // 6) out = relu((S2 @ W1 + 2*b1) * invden)  K=300 padded to 304 (19 steps)
    dense_gemm_kernel<<<dim3(5, BT_ / 128), 128>>>(gx, HLD, 19, W1_w, MEM_, MEM_,
                                                   W1_b, ginv, out, MEM_);
}